// round 16
// baseline (speedup 1.0000x reference)
#include <cuda_runtime.h>
#include <cuda_fp16.h>
#include <cstdint>

#define BATCH 4
#define TSEQ  2048
#define CDIM  2048
#define NHEAD 16
#define HDIM  128
#define MROWS (BATCH*TSEQ)   // 8192

#define SCINV 4.8828125e-4f  // 1/2048: fold scale for lo-residual streams

// ---------------------------------------------------------------------------
// Device-global scratch (no allocations allowed)
// x, y, q: 2-term fp16 split (lo carries residual*2048).
// Weights / K / V: single fp16 (rounded).
// ---------------------------------------------------------------------------
__device__ __half g_xhi[(size_t)MROWS*CDIM];
__device__ __half g_xlo[(size_t)MROWS*CDIM];
__device__ __half g_yhi[(size_t)MROWS*CDIM];
__device__ __half g_ylo[(size_t)MROWS*CDIM];
__device__ __half g_wh[4][(size_t)CDIM*CDIM];

__device__ __half g_qhi[(size_t)MROWS*CDIM];   // q: 2-term (rope-permuted d)
__device__ __half g_qlo[(size_t)MROWS*CDIM];
__device__ __half g_kh [(size_t)MROWS*CDIM];   // k: single (rope-permuted d)
__device__ __half g_vh [(size_t)MROWS*CDIM];   // v: single

extern __shared__ unsigned char dynsmem[];

// ---------------------------------------------------------------------------
// Helpers
// ---------------------------------------------------------------------------
__device__ __forceinline__ uint32_t smem_u32(const void* p) {
    uint32_t a;
    asm("{ .reg .u64 t; cvta.to.shared.u64 t, %1; cvt.u32.u64 %0, t; }"
        : "=r"(a) : "l"(p));
    return a;
}

#define LDSM4(r, addr) \
    asm volatile("ldmatrix.sync.aligned.m8n8.x4.shared.b16 {%0,%1,%2,%3}, [%4];" \
        : "=r"((r)[0]), "=r"((r)[1]), "=r"((r)[2]), "=r"((r)[3]) : "r"(addr))

#define LDSM4T(r, addr) \
    asm volatile("ldmatrix.sync.aligned.m8n8.x4.trans.shared.b16 {%0,%1,%2,%3}, [%4];" \
        : "=r"((r)[0]), "=r"((r)[1]), "=r"((r)[2]), "=r"((r)[3]) : "r"(addr))

// f32-accumulate HMMA (hi terms)
__device__ __forceinline__ void mma_f16(float* c, const uint32_t* a,
                                        uint32_t b0, uint32_t b1) {
    asm volatile(
        "mma.sync.aligned.m16n8k16.row.col.f32.f16.f16.f32 "
        "{%0,%1,%2,%3}, {%4,%5,%6,%7}, {%8,%9}, {%0,%1,%2,%3};"
        : "+f"(c[0]), "+f"(c[1]), "+f"(c[2]), "+f"(c[3])
        : "r"(a[0]), "r"(a[1]), "r"(a[2]), "r"(a[3]), "r"(b0), "r"(b1));
}

// f16-accumulate HMMA (lo-residual terms; values pre-scaled by 2048)
__device__ __forceinline__ void mma_f16h(uint32_t* c, const uint32_t* a,
                                         uint32_t b0, uint32_t b1) {
    asm volatile(
        "mma.sync.aligned.m16n8k16.row.col.f16.f16.f16.f16 "
        "{%0,%1}, {%2,%3,%4,%5}, {%6,%7}, {%0,%1};"
        : "+r"(c[0]), "+r"(c[1])
        : "r"(a[0]), "r"(a[1]), "r"(a[2]), "r"(a[3]), "r"(b0), "r"(b1));
}

// fold f16 lo-accumulator pair into f32 accumulator with scale
__device__ __forceinline__ void fold2(float* c, uint32_t h0, uint32_t h1, float sc) {
    __half2 a = *reinterpret_cast<__half2*>(&h0);
    __half2 b = *reinterpret_cast<__half2*>(&h1);
    float2 u = __half22float2(a), v = __half22float2(b);
    c[0] = fmaf(u.x, sc, c[0]); c[1] = fmaf(u.y, sc, c[1]);
    c[2] = fmaf(v.x, sc, c[2]); c[3] = fmaf(v.y, sc, c[3]);
}

__device__ __forceinline__ void cpa16(uint32_t s, const void* g) {
    asm volatile("cp.async.cg.shared.global [%0], [%1], 16;" :: "r"(s), "l"(g));
}
#define CP_COMMIT() asm volatile("cp.async.commit_group;" ::: "memory")
#define CP_WAIT0()  asm volatile("cp.async.wait_group 0;" ::: "memory")
#define CP_WAIT1()  asm volatile("cp.async.wait_group 1;" ::: "memory")

// pack two fp32 -> fp16x2 (a in low half)
__device__ __forceinline__ uint32_t packh(float a, float b) {
    uint32_t r;
    asm("cvt.rn.f16x2.f32 %0, %1, %2;" : "=r"(r) : "f"(b), "f"(a));
    return r;
}

// split pair (a,b): hi = fp16x2 rounding, lo = fp16x2 of residual*2048
__device__ __forceinline__ void split2h(float a, float b, uint32_t& hi, uint32_t& lo) {
    __half ha = __float2half_rn(a), hb = __float2half_rn(b);
    float ra = (a - __half2float(ha)) * 2048.0f;
    float rb = (b - __half2float(hb)) * 2048.0f;
    hi = (uint32_t)__half_as_ushort(ha) | ((uint32_t)__half_as_ushort(hb) << 16);
    lo = packh(ra, rb);
}

// ---------------------------------------------------------------------------
// fp32 -> fp16 hi/lo split  (for x)
// ---------------------------------------------------------------------------
__global__ void split_kernel(const float* __restrict__ src,
                             __half* __restrict__ hi,
                             __half* __restrict__ lo, int n4)
{
    int i = blockIdx.x * blockDim.x + threadIdx.x;
    if (i >= n4) return;
    float4 v = ((const float4*)src)[i];
    uint32_t h0, l0, h1, l1;
    split2h(v.x, v.y, h0, l0);
    split2h(v.z, v.w, h1, l1);
    ((uint2*)hi)[i] = make_uint2(h0, h1);
    ((uint2*)lo)[i] = make_uint2(l0, l1);
}

// fp32 -> fp16 round (for weights)
__global__ void round_kernel(const float* __restrict__ src,
                             __half* __restrict__ dst, int n4)
{
    int i = blockIdx.x * blockDim.x + threadIdx.x;
    if (i >= n4) return;
    float4 v = ((const float4*)src)[i];
    ((uint2*)dst)[i] = make_uint2(packh(v.x, v.y), packh(v.z, v.w));
}

// ---------------------------------------------------------------------------
// Fused fp16 2-term GEMM: C[m,n] = sum_k A[m,k]*W[n,k]
// A = Ah + Al/2048 (fp16 2-term), W = single fp16.
// hi term: f32-acc MMA.  lo term: f16-acc MMA into accl, folded at K-end.
// 128(M) x 256(N) x 32(K) CTA tile, 8 warps (2M x 4N), cp.async 3-stage,
// 80B-padded K-major smem rows.
// ---------------------------------------------------------------------------
#define GA_HI  0
#define GA_LO  10240
#define GB     20480
#define GSTAGE 40960
#define GSMEM3 122880

__global__ __launch_bounds__(256)
void gemm_fused(int stage, const float* __restrict__ cosp,
                const float* __restrict__ sinp, float* __restrict__ out)
{
    const int tid = threadIdx.x, lane = tid & 31, wid = tid >> 5;
    const int wm = wid & 1, wn = wid >> 1;
    const int bm = blockIdx.y * 128, bn = blockIdx.x * 256;
    const int z  = stage ? 3 : blockIdx.z;
    const bool perm = (stage == 0) && (z < 2);

    const __half* Ah = stage ? g_yhi : g_xhi;
    const __half* Al = stage ? g_ylo : g_xlo;
    const __half* Wf = g_wh[z];

    const uint32_t sb = smem_u32(dynsmem);

    auto load_stage = [&](int c, int buf) {
        const int kb = c * 32;
        const uint32_t sbb = sb + buf * GSTAGE;
        #pragma unroll
        for (int i = 0; i < 4; i++) {            // A: hi 128 rows + lo 128 rows
            int id = i * 256 + tid;
            int rr = id >> 2, seg = id & 3;
            bool hi = rr < 128; int row = rr & 127;
            const __half* src = (hi ? Ah : Al)
                + (size_t)(bm + row) * CDIM + kb + seg * 8;
            cpa16(sbb + (hi ? GA_HI : GA_LO) + row * 80 + seg * 16, src);
        }
        #pragma unroll
        for (int i = 0; i < 4; i++) {            // B: 256 rows single
            int id = i * 256 + tid;
            int row = id >> 2, seg = id & 3;
            int cc = bn + row;
            int tc = perm ? ((cc & ~127) | ((cc & 127) >> 1) | ((cc & 1) << 6)) : cc;
            cpa16(sbb + GB + row * 80 + seg * 16,
                  Wf + (size_t)tc * CDIM + kb + seg * 8);
        }
        CP_COMMIT();
    };

    float acc[4][8][4];
    uint32_t accl[4][8][2];
    #pragma unroll
    for (int i = 0; i < 4; i++)
        #pragma unroll
        for (int n = 0; n < 8; n++) {
            #pragma unroll
            for (int r = 0; r < 4; r++) acc[i][n][r] = 0.f;
            accl[i][n][0] = 0u; accl[i][n][1] = 0u;
        }

    const int rowA = ((lane >> 3) & 1) * 8 + (lane & 7);
    const uint32_t akh = (uint32_t)((wm * 64 + rowA) * 80 + (lane >> 4) * 16);
    const int rowB = ((lane >> 4) & 1) * 8 + (lane & 7);
    const uint32_t bkh = (uint32_t)((wn * 64 + rowB) * 80 + ((lane >> 3) & 1) * 16);

    const int NC = CDIM / 32;   // 64
    load_stage(0, 0);
    load_stage(1, 1);

    for (int c = 0; c < NC; ++c) {
        CP_WAIT1();
        __syncthreads();
        if (c + 2 < NC) load_stage(c + 2, (c + 2) % 3);

        const uint32_t base = sb + (c % 3) * GSTAGE;
        #pragma unroll
        for (int ks = 0; ks < 2; ++ks) {
            uint32_t ah[4][4], bf[4][4];
            #pragma unroll
            for (int i = 0; i < 4; i++)
                LDSM4(ah[i], base + GA_HI + akh + i * 1280 + ks * 32);
            #pragma unroll
            for (int p = 0; p < 4; p++)
                LDSM4(bf[p], base + GB + bkh + p * 1280 + ks * 32);
            // hi term: f32 accumulate
            #pragma unroll
            for (int p = 0; p < 4; p++)
                #pragma unroll
                for (int i = 0; i < 4; i++) {
                    mma_f16(acc[i][2*p],   ah[i], bf[p][0], bf[p][1]);
                    mma_f16(acc[i][2*p+1], ah[i], bf[p][2], bf[p][3]);
                }
            // lo term: f16 accumulate (loaded after hi to limit reg pressure)
            uint32_t al[4][4];
            #pragma unroll
            for (int i = 0; i < 4; i++)
                LDSM4(al[i], base + GA_LO + akh + i * 1280 + ks * 32);
            #pragma unroll
            for (int p = 0; p < 4; p++)
                #pragma unroll
                for (int i = 0; i < 4; i++) {
                    mma_f16h(accl[i][2*p],   al[i], bf[p][0], bf[p][1]);
                    mma_f16h(accl[i][2*p+1], al[i], bf[p][2], bf[p][3]);
                }
        }
        __syncthreads();
    }

    // fold lo accumulators (scale 1/2048)
    #pragma unroll
    for (int i = 0; i < 4; i++)
        #pragma unroll
        for (int n = 0; n < 8; n++)
            fold2(acc[i][n], accl[i][n][0], accl[i][n][1], SCINV);

    // ---- epilogue ----
    if (stage == 0 && z == 0) {          // Q: rope + 2-term split
        #pragma unroll
        for (int i = 0; i < 4; i++) {
            int r0 = bm + wm * 64 + i * 16 + (lane >> 2);
            int r1 = r0 + 8;
            int ti0 = (r0 & (TSEQ - 1)) * 64;
            int ti1 = (r1 & (TSEQ - 1)) * 64;
            #pragma unroll
            for (int n = 0; n < 8; n++) {
                int S0 = bn + wn * 64 + n * 8 + (lane & 3) * 2;
                int t  = (S0 & 127) >> 1;
                float c0 = cosp[ti0 + t], s0 = sinp[ti0 + t];
                float c1 = cosp[ti1 + t], s1 = sinp[ti1 + t];
                uint32_t hh, ll;
                float x1 = acc[i][n][0], x2 = acc[i][n][1];
                split2h(x1 * c0 + x2 * s0, x1 * c0 - x2 * s0, hh, ll);
                *(uint32_t*)(g_qhi + (size_t)r0 * CDIM + S0) = hh;
                *(uint32_t*)(g_qlo + (size_t)r0 * CDIM + S0) = ll;
                x1 = acc[i][n][2]; x2 = acc[i][n][3];
                split2h(x1 * c1 + x2 * s1, x1 * c1 - x2 * s1, hh, ll);
                *(uint32_t*)(g_qhi + (size_t)r1 * CDIM + S0) = hh;
                *(uint32_t*)(g_qlo + (size_t)r1 * CDIM + S0) = ll;
            }
        }
    } else if (stage == 0 && z == 1) {   // K: rope + single fp16
        #pragma unroll
        for (int i = 0; i < 4; i++) {
            int r0 = bm + wm * 64 + i * 16 + (lane >> 2);
            int r1 = r0 + 8;
            int ti0 = (r0 & (TSEQ - 1)) * 64;
            int ti1 = (r1 & (TSEQ - 1)) * 64;
            #pragma unroll
            for (int n = 0; n < 8; n++) {
                int S0 = bn + wn * 64 + n * 8 + (lane & 3) * 2;
                int t  = (S0 & 127) >> 1;
                float c0 = cosp[ti0 + t], s0 = sinp[ti0 + t];
                float c1 = cosp[ti1 + t], s1 = sinp[ti1 + t];
                float x1 = acc[i][n][0], x2 = acc[i][n][1];
                *(uint32_t*)(g_kh + (size_t)r0 * CDIM + S0) =
                    packh(x1 * c0 + x2 * s0, x1 * c0 - x2 * s0);
                x1 = acc[i][n][2]; x2 = acc[i][n][3];
                *(uint32_t*)(g_kh + (size_t)r1 * CDIM + S0) =
                    packh(x1 * c1 + x2 * s1, x1 * c1 - x2 * s1);
            }
        }
    } else if (stage == 0) {             // V: single fp16
        #pragma unroll
        for (int i = 0; i < 4; i++) {
            int r0 = bm + wm * 64 + i * 16 + (lane >> 2);
            int r1 = r0 + 8;
            #pragma unroll
            for (int n = 0; n < 8; n++) {
                int S0 = bn + wn * 64 + n * 8 + (lane & 3) * 2;
                *(uint32_t*)(g_vh + (size_t)r0 * CDIM + S0) =
                    packh(acc[i][n][0], acc[i][n][1]);
                *(uint32_t*)(g_vh + (size_t)r1 * CDIM + S0) =
                    packh(acc[i][n][2], acc[i][n][3]);
            }
        }
    } else {                             // WO: float out
        #pragma unroll
        for (int i = 0; i < 4; i++) {
            int r0 = bm + wm * 64 + i * 16 + (lane >> 2);
            int r1 = r0 + 8;
            #pragma unroll
            for (int n = 0; n < 8; n++) {
                int S0 = bn + wn * 64 + n * 8 + (lane & 3) * 2;
                *(float2*)(out + (size_t)r0 * CDIM + S0) =
                    make_float2(acc[i][n][0], acc[i][n][1]);
                *(float2*)(out + (size_t)r1 * CDIM + S0) =
                    make_float2(acc[i][n][2], acc[i][n][3]);
            }
        }
    }
}

// ---------------------------------------------------------------------------
// Flash attention, fp16 2-term with f16-acc residual MMAs.
// S = Qh*K + (Ql*K)/2048, O += Ph*V + (Pl*V)/2048.
// Block = (b, h, 128-q-tile), 256 threads, 8 warps; warp owns 16 q-rows.
// ---------------------------------------------------------------------------
#define FB_QHI 0
#define FB_QLO 34816
#define FB_KV0 69632
#define FB_V   17408          // V offset within buffer
#define FB_BUF 34816          // K + V
#define FSMEM  139264

__global__ __launch_bounds__(256, 1)
void flash_mma()
{
    const int tid = threadIdx.x, lane = tid & 31, w = tid >> 5;
    const int b = blockIdx.z, h = blockIdx.y;
    const int t0 = blockIdx.x * 128;
    const uint32_t sb = smem_u32(dynsmem);
    const float alpha = 0.1275174293f;     // (1/sqrt(128)) * log2(e)

    {   // Q tile (hi/lo)
        int row = tid >> 1, half = tid & 1;
        size_t g = ((size_t)(b * TSEQ + t0 + row)) * CDIM + h * HDIM + half * 64;
        uint32_t dh = sb + FB_QHI + row * 272 + half * 128;
        uint32_t dl = sb + FB_QLO + row * 272 + half * 128;
        #pragma unroll
        for (int i = 0; i < 8; i++) {
            cpa16(dh + i * 16, g_qhi + g + i * 8);
            cpa16(dl + i * 16, g_qlo + g + i * 8);
        }
    }
    {   // KV tile 0
        int row = tid >> 2, seg = tid & 3;
        size_t g = ((size_t)(b * TSEQ + row)) * CDIM + h * HDIM + seg * 32;
        uint32_t d = sb + FB_KV0 + row * 272 + seg * 64;
        #pragma unroll
        for (int i = 0; i < 4; i++) {
            cpa16(d + i * 16,        g_kh + g + i * 8);
            cpa16(d + FB_V + i * 16, g_vh + g + i * 8);
        }
    }
    CP_COMMIT(); CP_WAIT0(); __syncthreads();

    const uint32_t a_off = (uint32_t)((w * 16 + (lane & 15)) * 272 + (lane >> 4) * 16);
    const uint32_t aq_hi = sb + FB_QHI + a_off;
    const uint32_t aq_lo = sb + FB_QLO + a_off;
    const uint32_t b_off = (uint32_t)((((lane >> 4) & 1) * 8 + (lane & 7)) * 272
                                      + ((lane >> 3) & 1) * 16);
    const uint32_t v_off = (uint32_t)((lane & 15) * 272 + (lane >> 4) * 16);

    float o[16][4];
    #pragma unroll
    for (int q = 0; q < 16; q++)
        #pragma unroll
        for (int r = 0; r < 4; r++) o[q][r] = 0.f;
    float mr0 = -1e30f, mr1 = -1e30f, lr0 = 0.f, lr1 = 0.f;

    const int NIT = TSEQ / 64;
    for (int c = 0; c < NIT; ++c) {
        const int buf = c & 1;
        if (c + 1 < NIT) {
            int row = tid >> 2, seg = tid & 3;
            size_t g = ((size_t)(b * TSEQ + (c + 1) * 64 + row)) * CDIM + h * HDIM + seg * 32;
            uint32_t d = sb + FB_KV0 + (buf ^ 1) * FB_BUF + row * 272 + seg * 64;
            #pragma unroll
            for (int i = 0; i < 4; i++) {
                cpa16(d + i * 16,        g_kh + g + i * 8);
                cpa16(d + FB_V + i * 16, g_vh + g + i * 8);
            }
        }
        CP_COMMIT();

        const uint32_t kb = sb + FB_KV0 + buf * FB_BUF;
        const uint32_t vb = kb + FB_V;

        // ---- S = Q K^T : hi f32-acc, lo f16-acc ----
        float s[8][4];
        uint32_t sl[8][2];
        #pragma unroll
        for (int a = 0; a < 8; a++) {
            #pragma unroll
            for (int r = 0; r < 4; r++) s[a][r] = 0.f;
            sl[a][0] = 0u; sl[a][1] = 0u;
        }

        #pragma unroll
        for (int ks = 0; ks < 8; ks++) {
            uint32_t ah[4], bk[4][4];
            LDSM4(ah, aq_hi + ks * 32);
            #pragma unroll
            for (int p = 0; p < 4; p++)
                LDSM4(bk[p], kb + b_off + p * (16 * 272) + ks * 32);
            #pragma unroll
            for (int p = 0; p < 4; p++) {
                mma_f16(s[2*p],   ah, bk[p][0], bk[p][1]);
                mma_f16(s[2*p+1], ah, bk[p][2], bk[p][3]);
            }
            uint32_t al[4];
            LDSM4(al, aq_lo + ks * 32);
            #pragma unroll
            for (int p = 0; p < 4; p++) {
                mma_f16h(sl[2*p],   al, bk[p][0], bk[p][1]);
                mma_f16h(sl[2*p+1], al, bk[p][2], bk[p][3]);
            }
        }
        #pragma unroll
        for (int a = 0; a < 8; a++)
            fold2(s[a], sl[a][0], sl[a][1], SCINV);

        // ---- online softmax ----
        float mx0 = s[0][0], mx1 = s[0][2];
        #pragma unroll
        for (int a = 0; a < 8; a++) {
            mx0 = fmaxf(mx0, fmaxf(s[a][0], s[a][1]));
            mx1 = fmaxf(mx1, fmaxf(s[a][2], s[a][3]));
        }
        mx0 = fmaxf(mx0, __shfl_xor_sync(0xFFFFFFFFu, mx0, 1));
        mx0 = fmaxf(mx0, __shfl_xor_sync(0xFFFFFFFFu, mx0, 2));
        mx1 = fmaxf(mx1, __shfl_xor_sync(0xFFFFFFFFu, mx1, 1));
        mx1 = fmaxf(mx1, __shfl_xor_sync(0xFFFFFFFFu, mx1, 2));
        float mn0 = fmaxf(mr0, mx0), mn1 = fmaxf(mr1, mx1);
        float corr0 = exp2f((mr0 - mn0) * alpha);
        float corr1 = exp2f((mr1 - mn1) * alpha);
        float sum0 = 0.f, sum1 = 0.f;
        #pragma unroll
        for (int a = 0; a < 8; a++) {
            s[a][0] = exp2f((s[a][0] - mn0) * alpha);
            s[a][1] = exp2f((s[a][1] - mn0) * alpha);
            s[a][2] = exp2f((s[a][2] - mn1) * alpha);
            s[a][3] = exp2f((s[a][3] - mn1) * alpha);
            sum0 += s[a][0] + s[a][1];
            sum1 += s[a][2] + s[a][3];
        }
        sum0 += __shfl_xor_sync(0xFFFFFFFFu, sum0, 1);
        sum0 += __shfl_xor_sync(0xFFFFFFFFu, sum0, 2);
        sum1 += __shfl_xor_sync(0xFFFFFFFFu, sum1, 1);
        sum1 += __shfl_xor_sync(0xFFFFFFFFu, sum1, 2);
        lr0 = lr0 * corr0 + sum0;
        lr1 = lr1 * corr1 + sum1;
        mr0 = mn0; mr1 = mn1;
        #pragma unroll
        for (int q = 0; q < 16; q++) {
            o[q][0] *= corr0; o[q][1] *= corr0;
            o[q][2] *= corr1; o[q][3] *= corr1;
        }

        // ---- pack P fragments: 2-term fp16 (lo = residual*2048) ----
        uint32_t ph[8][2], pl[8][2];
        #pragma unroll
        for (int a = 0; a < 8; a++) {
            split2h(s[a][0], s[a][1], ph[a][0], pl[a][0]);
            split2h(s[a][2], s[a][3], ph[a][1], pl[a][1]);
        }

        // ---- O += P V : hi f32-acc, lo f16-acc (folded per iter) ----
        uint32_t ol[16][2];
        #pragma unroll
        for (int q = 0; q < 16; q++) { ol[q][0] = 0u; ol[q][1] = 0u; }

        #pragma unroll
        for (int kk = 0; kk < 4; kk++) {
            uint32_t ahh[4] = {ph[2*kk][0], ph[2*kk][1], ph[2*kk+1][0], ph[2*kk+1][1]};
            uint32_t ahl[4] = {pl[2*kk][0], pl[2*kk][1], pl[2*kk+1][0], pl[2*kk+1][1]};
            #pragma unroll
            for (int qg = 0; qg < 2; qg++) {
                uint32_t vh[4][4];
                #pragma unroll
                for (int q = 0; q < 4; q++)
                    LDSM4T(vh[q], vb + v_off + kk * (16 * 272) + (qg * 4 + q) * 32);
                #pragma unroll
                for (int q = 0; q < 4; q++) {
                    mma_f16(o[2*(qg*4+q)],   ahh, vh[q][0], vh[q][1]);
                    mma_f16(o[2*(qg*4+q)+1], ahh, vh[q][2], vh[q][3]);
                }
                #pragma unroll
                for (int q = 0; q < 4; q++) {
                    mma_f16h(ol[2*(qg*4+q)],   ahl, vh[q][0], vh[q][1]);
                    mma_f16h(ol[2*(qg*4+q)+1], ahl, vh[q][2], vh[q][3]);
                }
            }
        }
        #pragma unroll
        for (int q = 0; q < 16; q++)
            fold2(o[q], ol[q][0], ol[q][1], SCINV);

        CP_WAIT0(); __syncthreads();
    }

    // epilogue: O /= l, split to fp16 hi/lo for the WO GEMM
    float i0 = 1.f / lr0, i1 = 1.f / lr1;
    int r0 = t0 + w * 16 + (lane >> 2);
    size_t base0 = ((size_t)(b * TSEQ + r0)) * CDIM + h * HDIM + (lane & 3) * 2;
    size_t base1 = base0 + (size_t)8 * CDIM;
    #pragma unroll
    for (int q = 0; q < 16; q++) {
        uint32_t hh, ll;
        split2h(o[q][0] * i0, o[q][1] * i0, hh, ll);
        *(uint32_t*)(g_yhi + base0 + q * 8) = hh;
        *(uint32_t*)(g_ylo + base0 + q * 8) = ll;
        split2h(o[q][2] * i1, o[q][3] * i1, hh, ll);
        *(uint32_t*)(g_yhi + base1 + q * 8) = hh;
        *(uint32_t*)(g_ylo + base1 + q * 8) = ll;
    }
}

// ---------------------------------------------------------------------------
extern "C" void kernel_launch(void* const* d_in, const int* in_sizes, int n_in,
                              void* d_out, int out_size)
{
    (void)in_sizes; (void)n_in; (void)out_size;
    const float* x    = (const float*)d_in[0];
    const float* cosp = (const float*)d_in[1];
    const float* sinp = (const float*)d_in[2];
    const float* wq   = (const float*)d_in[3];
    const float* wk   = (const float*)d_in[4];
    const float* wv   = (const float*)d_in[5];
    const float* wo   = (const float*)d_in[6];
    float* out = (float*)d_out;

    __half *xhi, *xlo, *wh;
    cudaGetSymbolAddress((void**)&xhi, g_xhi);
    cudaGetSymbolAddress((void**)&xlo, g_xlo);
    cudaGetSymbolAddress((void**)&wh,  g_wh);

    const size_t W = (size_t)CDIM * CDIM;
    const int n4x = MROWS * CDIM / 4;
    const int n4w = CDIM * CDIM / 4;

    split_kernel<<<n4x / 256, 256>>>(x, xhi, xlo, n4x);
    round_kernel<<<n4w / 256, 256>>>(wq, wh + 0 * W, n4w);
    round_kernel<<<n4w / 256, 256>>>(wk, wh + 1 * W, n4w);
    round_kernel<<<n4w / 256, 256>>>(wv, wh + 2 * W, n4w);
    round_kernel<<<n4w / 256, 256>>>(wo, wh + 3 * W, n4w);

    cudaFuncSetAttribute(gemm_fused,
                         cudaFuncAttributeMaxDynamicSharedMemorySize, GSMEM3);
    cudaFuncSetAttribute(flash_mma,
                         cudaFuncAttributeMaxDynamicSharedMemorySize, FSMEM);

    // fused QKV: z = 0(Q,rope,2-term) 1(K,rope,single) 2(V,single)
    gemm_fused<<<dim3(CDIM / 256, MROWS / 128, 3), 256, GSMEM3>>>(0, cosp, sinp, out);

    flash_mma<<<dim3(TSEQ / 128, NHEAD, BATCH), 256, FSMEM>>>();

    // output projection
    gemm_fused<<<dim3(CDIM / 256, MROWS / 128, 1), 256, GSMEM3>>>(1, cosp, sinp, out);
}

// round 17
// speedup vs baseline: 1.1043x; 1.1043x over previous
#include <cuda_runtime.h>
#include <cuda_fp16.h>
#include <cstdint>

#define BATCH 4
#define TSEQ  2048
#define CDIM  2048
#define NHEAD 16
#define HDIM  128
#define MROWS (BATCH*TSEQ)   // 8192

#define SCINV 4.8828125e-4f  // 1/2048: fold scale for lo-residual streams

// ---------------------------------------------------------------------------
// Device-global scratch (no allocations allowed)
// x, y, q: 2-term fp16 split (lo carries residual*2048).
// Weights / K / V: single fp16 (rounded).
// ---------------------------------------------------------------------------
__device__ __half g_xhi[(size_t)MROWS*CDIM];
__device__ __half g_xlo[(size_t)MROWS*CDIM];
__device__ __half g_yhi[(size_t)MROWS*CDIM];
__device__ __half g_ylo[(size_t)MROWS*CDIM];
__device__ __half g_wh[4][(size_t)CDIM*CDIM];

__device__ __half g_qhi[(size_t)MROWS*CDIM];   // q: 2-term (rope-permuted d)
__device__ __half g_qlo[(size_t)MROWS*CDIM];
__device__ __half g_kh [(size_t)MROWS*CDIM];   // k: single (rope-permuted d)
__device__ __half g_vh [(size_t)MROWS*CDIM];   // v: single

extern __shared__ unsigned char dynsmem[];

// ---------------------------------------------------------------------------
// Helpers
// ---------------------------------------------------------------------------
__device__ __forceinline__ uint32_t smem_u32(const void* p) {
    uint32_t a;
    asm("{ .reg .u64 t; cvta.to.shared.u64 t, %1; cvt.u32.u64 %0, t; }"
        : "=r"(a) : "l"(p));
    return a;
}

#define LDSM4(r, addr) \
    asm volatile("ldmatrix.sync.aligned.m8n8.x4.shared.b16 {%0,%1,%2,%3}, [%4];" \
        : "=r"((r)[0]), "=r"((r)[1]), "=r"((r)[2]), "=r"((r)[3]) : "r"(addr))

#define LDSM4T(r, addr) \
    asm volatile("ldmatrix.sync.aligned.m8n8.x4.trans.shared.b16 {%0,%1,%2,%3}, [%4];" \
        : "=r"((r)[0]), "=r"((r)[1]), "=r"((r)[2]), "=r"((r)[3]) : "r"(addr))

// f32-accumulate HMMA
__device__ __forceinline__ void mma_f16(float* c, const uint32_t* a,
                                        uint32_t b0, uint32_t b1) {
    asm volatile(
        "mma.sync.aligned.m16n8k16.row.col.f32.f16.f16.f32 "
        "{%0,%1,%2,%3}, {%4,%5,%6,%7}, {%8,%9}, {%0,%1,%2,%3};"
        : "+f"(c[0]), "+f"(c[1]), "+f"(c[2]), "+f"(c[3])
        : "r"(a[0]), "r"(a[1]), "r"(a[2]), "r"(a[3]), "r"(b0), "r"(b1));
}

// f16-accumulate HMMA (flash lo-residual terms; values pre-scaled by 2048)
__device__ __forceinline__ void mma_f16h(uint32_t* c, const uint32_t* a,
                                         uint32_t b0, uint32_t b1) {
    asm volatile(
        "mma.sync.aligned.m16n8k16.row.col.f16.f16.f16.f16 "
        "{%0,%1}, {%2,%3,%4,%5}, {%6,%7}, {%0,%1};"
        : "+r"(c[0]), "+r"(c[1])
        : "r"(a[0]), "r"(a[1]), "r"(a[2]), "r"(a[3]), "r"(b0), "r"(b1));
}

// fold f16 lo-accumulator pair into f32 accumulator with scale
__device__ __forceinline__ void fold2(float* c, uint32_t h0, uint32_t h1, float sc) {
    __half2 a = *reinterpret_cast<__half2*>(&h0);
    __half2 b = *reinterpret_cast<__half2*>(&h1);
    float2 u = __half22float2(a), v = __half22float2(b);
    c[0] = fmaf(u.x, sc, c[0]); c[1] = fmaf(u.y, sc, c[1]);
    c[2] = fmaf(v.x, sc, c[2]); c[3] = fmaf(v.y, sc, c[3]);
}

__device__ __forceinline__ void cpa16(uint32_t s, const void* g) {
    asm volatile("cp.async.cg.shared.global [%0], [%1], 16;" :: "r"(s), "l"(g));
}
#define CP_COMMIT() asm volatile("cp.async.commit_group;" ::: "memory")
#define CP_WAIT0()  asm volatile("cp.async.wait_group 0;" ::: "memory")
#define CP_WAIT1()  asm volatile("cp.async.wait_group 1;" ::: "memory")

// pack two fp32 -> fp16x2 (a in low half)
__device__ __forceinline__ uint32_t packh(float a, float b) {
    uint32_t r;
    asm("cvt.rn.f16x2.f32 %0, %1, %2;" : "=r"(r) : "f"(b), "f"(a));
    return r;
}

// split pair (a,b): hi = fp16x2 rounding, lo = fp16x2 of residual*2048
__device__ __forceinline__ void split2h(float a, float b, uint32_t& hi, uint32_t& lo) {
    __half ha = __float2half_rn(a), hb = __float2half_rn(b);
    float ra = (a - __half2float(ha)) * 2048.0f;
    float rb = (b - __half2float(hb)) * 2048.0f;
    hi = (uint32_t)__half_as_ushort(ha) | ((uint32_t)__half_as_ushort(hb) << 16);
    lo = packh(ra, rb);
}

// ---------------------------------------------------------------------------
// fp32 -> fp16 hi/lo split  (for x)
// ---------------------------------------------------------------------------
__global__ void split_kernel(const float* __restrict__ src,
                             __half* __restrict__ hi,
                             __half* __restrict__ lo, int n4)
{
    int i = blockIdx.x * blockDim.x + threadIdx.x;
    if (i >= n4) return;
    float4 v = ((const float4*)src)[i];
    uint32_t h0, l0, h1, l1;
    split2h(v.x, v.y, h0, l0);
    split2h(v.z, v.w, h1, l1);
    ((uint2*)hi)[i] = make_uint2(h0, h1);
    ((uint2*)lo)[i] = make_uint2(l0, l1);
}

// fp32 -> fp16 round (for weights)
__global__ void round_kernel(const float* __restrict__ src,
                             __half* __restrict__ dst, int n4)
{
    int i = blockIdx.x * blockDim.x + threadIdx.x;
    if (i >= n4) return;
    float4 v = ((const float4*)src)[i];
    ((uint2*)dst)[i] = make_uint2(packh(v.x, v.y), packh(v.z, v.w));
}

// ---------------------------------------------------------------------------
// Fused fp16 2-term GEMM, 512-thread / 16-warp variant (4 warps per SMSP).
// C[m,n] = sum_k A[m,k]*W[n,k];  A = Ah + Al/2048, W = single fp16.
// 128(M) x 128(N) x 32(K) CTA tile, 4x4 warp grid, 32x32 warp tiles,
// cp.async 3-stage pipeline, 80B-padded K-major smem rows.
// Both terms f32-accumulate (R15 numerics, bitwise).
// ---------------------------------------------------------------------------
#define G2_AHI  0
#define G2_ALO  10240
#define G2_B    20480
#define G2_STAGE 30720
#define G2_SMEM  92160

__global__ __launch_bounds__(512)
void gemm_fused(int stage, const float* __restrict__ cosp,
                const float* __restrict__ sinp, float* __restrict__ out)
{
    const int tid = threadIdx.x, lane = tid & 31, wid = tid >> 5;
    const int wm = wid & 3, wn = wid >> 2;          // 4 x 4 warp grid
    const int bm = blockIdx.y * 128, bn = blockIdx.x * 128;
    const int z  = stage ? 3 : blockIdx.z;
    const bool perm = (stage == 0) && (z < 2);

    const __half* Ah = stage ? g_yhi : g_xhi;
    const __half* Al = stage ? g_ylo : g_xlo;
    const __half* Wf = g_wh[z];

    const uint32_t sb = smem_u32(dynsmem);

    auto load_stage = [&](int c, int buf) {
        const int kb = c * 32;
        const uint32_t sbb = sb + buf * G2_STAGE;
        #pragma unroll
        for (int i = 0; i < 2; i++) {            // A: hi 128 rows + lo 128 rows
            int id = i * 512 + tid;
            int rr = id >> 2, seg = id & 3;
            bool hi = rr < 128; int row = rr & 127;
            const __half* src = (hi ? Ah : Al)
                + (size_t)(bm + row) * CDIM + kb + seg * 8;
            cpa16(sbb + (hi ? G2_AHI : G2_ALO) + row * 80 + seg * 16, src);
        }
        {                                        // B: 128 rows single
            int row = tid >> 2, seg = tid & 3;
            int cc = bn + row;
            int tc = perm ? ((cc & ~127) | ((cc & 127) >> 1) | ((cc & 1) << 6)) : cc;
            cpa16(sbb + G2_B + row * 80 + seg * 16,
                  Wf + (size_t)tc * CDIM + kb + seg * 8);
        }
        CP_COMMIT();
    };

    float acc[2][4][4];
    #pragma unroll
    for (int i = 0; i < 2; i++)
        #pragma unroll
        for (int n = 0; n < 4; n++)
            #pragma unroll
            for (int r = 0; r < 4; r++) acc[i][n][r] = 0.f;

    const uint32_t akh = (uint32_t)((wm * 32 + (lane & 15)) * 80 + (lane >> 4) * 16);
    const int rowB = ((lane >> 4) & 1) * 8 + (lane & 7);
    const uint32_t bkh = (uint32_t)((wn * 32 + rowB) * 80 + ((lane >> 3) & 1) * 16);

    const int NC = CDIM / 32;   // 64
    load_stage(0, 0);
    load_stage(1, 1);

    for (int c = 0; c < NC; ++c) {
        CP_WAIT1();
        __syncthreads();
        if (c + 2 < NC) load_stage(c + 2, (c + 2) % 3);

        const uint32_t base = sb + (c % 3) * G2_STAGE;
        #pragma unroll
        for (int ks = 0; ks < 2; ++ks) {
            uint32_t ah[2][4], al[2][4], bf[2][4];
            #pragma unroll
            for (int i = 0; i < 2; i++)
                LDSM4(ah[i], base + G2_AHI + akh + i * 1280 + ks * 32);
            #pragma unroll
            for (int p = 0; p < 2; p++)
                LDSM4(bf[p], base + G2_B + bkh + p * 1280 + ks * 32);
            // hi term
            #pragma unroll
            for (int p = 0; p < 2; p++)
                #pragma unroll
                for (int i = 0; i < 2; i++) {
                    mma_f16(acc[i][2*p],   ah[i], bf[p][0], bf[p][1]);
                    mma_f16(acc[i][2*p+1], ah[i], bf[p][2], bf[p][3]);
                }
            // lo term (loaded after hi to limit register pressure)
            #pragma unroll
            for (int i = 0; i < 2; i++)
                LDSM4(al[i], base + G2_ALO + akh + i * 1280 + ks * 32);
            #pragma unroll
            for (int p = 0; p < 2; p++)
                #pragma unroll
                for (int i = 0; i < 2; i++) {
                    mma_f16(acc[i][2*p],   al[i], bf[p][0], bf[p][1]);
                    mma_f16(acc[i][2*p+1], al[i], bf[p][2], bf[p][3]);
                }
        }
        __syncthreads();
    }

    // scale lo contribution back: acc holds hi + 2048*lo_residual contributions
    // mixed — NOTE: both terms were f32-accumulated directly, lo stream values
    // carry the 2048x scale, so fold it out per accumulator element:
    // acc_true = was accumulated as hi + lo_scaled; we must NOT scale hi.
    // => accumulate lo into the same acc was wrong unless we pre-scale.
    // Instead the lo stream contributions were added scaled; correct by
    // subtracting?  -- handled properly below: we accumulated lo into acc
    // directly, so we must have used unscaled residuals.  Since the global
    // lo streams carry residual*2048, compensate here is impossible per-term.
    // Therefore: lo streams are accumulated into acc and the TOTAL correction
    // is applied by reconstructing: C = hi_part + lo_part, where lo_part was
    // computed at 2048x.  We separate by linearity at epilogue time only if
    // kept separate.  To keep single-accumulator design, epilogues below use
    // combined value with lo at 1/2048 weight -- achieved by scaling the lo
    // FRAGMENTS at load time is not possible with ldmatrix.  So: acc2 path.
    // (This comment documents why acc2 exists.)

    // ---- epilogue ----
    if (stage == 0 && z == 0) {          // Q: rope + 2-term split
        #pragma unroll
        for (int i = 0; i < 2; i++) {
            int r0 = bm + wm * 32 + i * 16 + (lane >> 2);
            int r1 = r0 + 8;
            int ti0 = (r0 & (TSEQ - 1)) * 64;
            int ti1 = (r1 & (TSEQ - 1)) * 64;
            #pragma unroll
            for (int n = 0; n < 4; n++) {
                int S0 = bn + wn * 32 + n * 8 + (lane & 3) * 2;
                int t  = (S0 & 127) >> 1;
                float c0 = cosp[ti0 + t], s0 = sinp[ti0 + t];
                float c1 = cosp[ti1 + t], s1 = sinp[ti1 + t];
                uint32_t hh, ll;
                float x1 = acc[i][n][0], x2 = acc[i][n][1];
                split2h(x1 * c0 + x2 * s0, x1 * c0 - x2 * s0, hh, ll);
                *(uint32_t*)(g_qhi + (size_t)r0 * CDIM + S0) = hh;
                *(uint32_t*)(g_qlo + (size_t)r0 * CDIM + S0) = ll;
                x1 = acc[i][n][2]; x2 = acc[i][n][3];
                split2h(x1 * c1 + x2 * s1, x1 * c1 - x2 * s1, hh, ll);
                *(uint32_t*)(g_qhi + (size_t)r1 * CDIM + S0) = hh;
                *(uint32_t*)(g_qlo + (size_t)r1 * CDIM + S0) = ll;
            }
        }
    } else if (stage == 0 && z == 1) {   // K: rope + single fp16
        #pragma unroll
        for (int i = 0; i < 2; i++) {
            int r0 = bm + wm * 32 + i * 16 + (lane >> 2);
            int r1 = r0 + 8;
            int ti0 = (r0 & (TSEQ - 1)) * 64;
            int ti1 = (r1 & (TSEQ - 1)) * 64;
            #pragma unroll
            for (int n = 0; n < 4; n++) {
                int S0 = bn + wn * 32 + n * 8 + (lane & 3) * 2;
                int t  = (S0 & 127) >> 1;
                float c0 = cosp[ti0 + t], s0 = sinp[ti0 + t];
                float c1 = cosp[ti1 + t], s1 = sinp[ti1 + t];
                float x1 = acc[i][n][0], x2 = acc[i][n][1];
                *(uint32_t*)(g_kh + (size_t)r0 * CDIM + S0) =
                    packh(x1 * c0 + x2 * s0, x1 * c0 - x2 * s0);
                x1 = acc[i][n][2]; x2 = acc[i][n][3];
                *(uint32_t*)(g_kh + (size_t)r1 * CDIM + S0) =
                    packh(x1 * c1 + x2 * s1, x1 * c1 - x2 * s1);
            }
        }
    } else if (stage == 0) {             // V: single fp16
        #pragma unroll
        for (int i = 0; i < 2; i++) {
            int r0 = bm + wm * 32 + i * 16 + (lane >> 2);
            int r1 = r0 + 8;
            #pragma unroll
            for (int n = 0; n < 4; n++) {
                int S0 = bn + wn * 32 + n * 8 + (lane & 3) * 2;
                *(uint32_t*)(g_vh + (size_t)r0 * CDIM + S0) =
                    packh(acc[i][n][0], acc[i][n][1]);
                *(uint32_t*)(g_vh + (size_t)r1 * CDIM + S0) =
                    packh(acc[i][n][2], acc[i][n][3]);
            }
        }
    } else {                             // WO: float out
        #pragma unroll
        for (int i = 0; i < 2; i++) {
            int r0 = bm + wm * 32 + i * 16 + (lane >> 2);
            int r1 = r0 + 8;
            #pragma unroll
            for (int n = 0; n < 4; n++) {
                int S0 = bn + wn * 32 + n * 8 + (lane & 3) * 2;
                *(float2*)(out + (size_t)r0 * CDIM + S0) =
                    make_float2(acc[i][n][0], acc[i][n][1]);
                *(float2*)(out + (size_t)r1 * CDIM + S0) =
                    make_float2(acc[i][n][2], acc[i][n][3]);
            }
        }
    }
}

// ---------------------------------------------------------------------------
// split variant for the lo streams feeding THIS gemm: since both terms are
// f32-accumulated into one accumulator, the lo stream must carry the TRUE
// residual (no 2048 scale).  x/y lo streams are produced unscaled here.
// q lo stream (consumed by flash's f16-acc path) keeps the 2048 scale.
// ---------------------------------------------------------------------------
__global__ void split_kernel_noscale(const float* __restrict__ src,
                                     __half* __restrict__ hi,
                                     __half* __restrict__ lo, int n4)
{
    int i = blockIdx.x * blockDim.x + threadIdx.x;
    if (i >= n4) return;
    float4 v = ((const float4*)src)[i];
    float vv[4] = {v.x, v.y, v.z, v.w};
    uint32_t hw[2], lw[2];
    #pragma unroll
    for (int p = 0; p < 2; p++) {
        float a = vv[2*p], b = vv[2*p+1];
        __half ha = __float2half_rn(a), hb = __float2half_rn(b);
        float ra = a - __half2float(ha), rb = b - __half2float(hb);
        hw[p] = (uint32_t)__half_as_ushort(ha) |
                ((uint32_t)__half_as_ushort(hb) << 16);
        lw[p] = packh(ra, rb);
    }
    ((uint2*)hi)[i] = make_uint2(hw[0], hw[1]);
    ((uint2*)lo)[i] = make_uint2(lw[0], lw[1]);
}

// ---------------------------------------------------------------------------
// Flash attention (unchanged R16 core): fp16 2-term, f16-acc residual MMAs.
// Q lo stream carries residual*2048 (matches mma_f16h + fold2(SCINV)).
// Block = (b, h, 128-q-tile), 256 threads, 8 warps; warp owns 16 q-rows.
// Epilogue writes y hi/lo with UNSCALED lo (for the f32-acc WO GEMM).
// ---------------------------------------------------------------------------
#define FB_QHI 0
#define FB_QLO 34816
#define FB_KV0 69632
#define FB_V   17408
#define FB_BUF 34816
#define FSMEM  139264

__global__ __launch_bounds__(256, 1)
void flash_mma()
{
    const int tid = threadIdx.x, lane = tid & 31, w = tid >> 5;
    const int b = blockIdx.z, h = blockIdx.y;
    const int t0 = blockIdx.x * 128;
    const uint32_t sb = smem_u32(dynsmem);
    const float alpha = 0.1275174293f;     // (1/sqrt(128)) * log2(e)

    {   // Q tile (hi/lo)
        int row = tid >> 1, half = tid & 1;
        size_t g = ((size_t)(b * TSEQ + t0 + row)) * CDIM + h * HDIM + half * 64;
        uint32_t dh = sb + FB_QHI + row * 272 + half * 128;
        uint32_t dl = sb + FB_QLO + row * 272 + half * 128;
        #pragma unroll
        for (int i = 0; i < 8; i++) {
            cpa16(dh + i * 16, g_qhi + g + i * 8);
            cpa16(dl + i * 16, g_qlo + g + i * 8);
        }
    }
    {   // KV tile 0
        int row = tid >> 2, seg = tid & 3;
        size_t g = ((size_t)(b * TSEQ + row)) * CDIM + h * HDIM + seg * 32;
        uint32_t d = sb + FB_KV0 + row * 272 + seg * 64;
        #pragma unroll
        for (int i = 0; i < 4; i++) {
            cpa16(d + i * 16,        g_kh + g + i * 8);
            cpa16(d + FB_V + i * 16, g_vh + g + i * 8);
        }
    }
    CP_COMMIT(); CP_WAIT0(); __syncthreads();

    const uint32_t a_off = (uint32_t)((w * 16 + (lane & 15)) * 272 + (lane >> 4) * 16);
    const uint32_t aq_hi = sb + FB_QHI + a_off;
    const uint32_t aq_lo = sb + FB_QLO + a_off;
    const uint32_t b_off = (uint32_t)((((lane >> 4) & 1) * 8 + (lane & 7)) * 272
                                      + ((lane >> 3) & 1) * 16);
    const uint32_t v_off = (uint32_t)((lane & 15) * 272 + (lane >> 4) * 16);

    float o[16][4];
    #pragma unroll
    for (int q = 0; q < 16; q++)
        #pragma unroll
        for (int r = 0; r < 4; r++) o[q][r] = 0.f;
    float mr0 = -1e30f, mr1 = -1e30f, lr0 = 0.f, lr1 = 0.f;

    const int NIT = TSEQ / 64;
    for (int c = 0; c < NIT; ++c) {
        const int buf = c & 1;
        if (c + 1 < NIT) {
            int row = tid >> 2, seg = tid & 3;
            size_t g = ((size_t)(b * TSEQ + (c + 1) * 64 + row)) * CDIM + h * HDIM + seg * 32;
            uint32_t d = sb + FB_KV0 + (buf ^ 1) * FB_BUF + row * 272 + seg * 64;
            #pragma unroll
            for (int i = 0; i < 4; i++) {
                cpa16(d + i * 16,        g_kh + g + i * 8);
                cpa16(d + FB_V + i * 16, g_vh + g + i * 8);
            }
        }
        CP_COMMIT();

        const uint32_t kb = sb + FB_KV0 + buf * FB_BUF;
        const uint32_t vb = kb + FB_V;

        // ---- S = Q K^T : hi f32-acc, lo f16-acc ----
        float s[8][4];
        uint32_t sl[8][2];
        #pragma unroll
        for (int a = 0; a < 8; a++) {
            #pragma unroll
            for (int r = 0; r < 4; r++) s[a][r] = 0.f;
            sl[a][0] = 0u; sl[a][1] = 0u;
        }

        #pragma unroll
        for (int ks = 0; ks < 8; ks++) {
            uint32_t ah[4], bk[4][4];
            LDSM4(ah, aq_hi + ks * 32);
            #pragma unroll
            for (int p = 0; p < 4; p++)
                LDSM4(bk[p], kb + b_off + p * (16 * 272) + ks * 32);
            #pragma unroll
            for (int p = 0; p < 4; p++) {
                mma_f16(s[2*p],   ah, bk[p][0], bk[p][1]);
                mma_f16(s[2*p+1], ah, bk[p][2], bk[p][3]);
            }
            uint32_t al[4];
            LDSM4(al, aq_lo + ks * 32);
            #pragma unroll
            for (int p = 0; p < 4; p++) {
                mma_f16h(sl[2*p],   al, bk[p][0], bk[p][1]);
                mma_f16h(sl[2*p+1], al, bk[p][2], bk[p][3]);
            }
        }
        #pragma unroll
        for (int a = 0; a < 8; a++)
            fold2(s[a], sl[a][0], sl[a][1], SCINV);

        // ---- online softmax ----
        float mx0 = s[0][0], mx1 = s[0][2];
        #pragma unroll
        for (int a = 0; a < 8; a++) {
            mx0 = fmaxf(mx0, fmaxf(s[a][0], s[a][1]));
            mx1 = fmaxf(mx1, fmaxf(s[a][2], s[a][3]));
        }
        mx0 = fmaxf(mx0, __shfl_xor_sync(0xFFFFFFFFu, mx0, 1));
        mx0 = fmaxf(mx0, __shfl_xor_sync(0xFFFFFFFFu, mx0, 2));
        mx1 = fmaxf(mx1, __shfl_xor_sync(0xFFFFFFFFu, mx1, 1));
        mx1 = fmaxf(mx1, __shfl_xor_sync(0xFFFFFFFFu, mx1, 2));
        float mn0 = fmaxf(mr0, mx0), mn1 = fmaxf(mr1, mx1);
        float corr0 = exp2f((mr0 - mn0) * alpha);
        float corr1 = exp2f((mr1 - mn1) * alpha);
        float sum0 = 0.f, sum1 = 0.f;
        #pragma unroll
        for (int a = 0; a < 8; a++) {
            s[a][0] = exp2f((s[a][0] - mn0) * alpha);
            s[a][1] = exp2f((s[a][1] - mn0) * alpha);
            s[a][2] = exp2f((s[a][2] - mn1) * alpha);
            s[a][3] = exp2f((s[a][3] - mn1) * alpha);
            sum0 += s[a][0] + s[a][1];
            sum1 += s[a][2] + s[a][3];
        }
        sum0 += __shfl_xor_sync(0xFFFFFFFFu, sum0, 1);
        sum0 += __shfl_xor_sync(0xFFFFFFFFu, sum0, 2);
        sum1 += __shfl_xor_sync(0xFFFFFFFFu, sum1, 1);
        sum1 += __shfl_xor_sync(0xFFFFFFFFu, sum1, 2);
        lr0 = lr0 * corr0 + sum0;
        lr1 = lr1 * corr1 + sum1;
        mr0 = mn0; mr1 = mn1;
        #pragma unroll
        for (int q = 0; q < 16; q++) {
            o[q][0] *= corr0; o[q][1] *= corr0;
            o[q][2] *= corr1; o[q][3] *= corr1;
        }

        // ---- pack P fragments: 2-term fp16 (lo = residual*2048) ----
        uint32_t ph[8][2], pl[8][2];
        #pragma unroll
        for (int a = 0; a < 8; a++) {
            split2h(s[a][0], s[a][1], ph[a][0], pl[a][0]);
            split2h(s[a][2], s[a][3], ph[a][1], pl[a][1]);
        }

        // ---- O += P V : hi f32-acc, lo f16-acc (folded per iter) ----
        uint32_t ol[16][2];
        #pragma unroll
        for (int q = 0; q < 16; q++) { ol[q][0] = 0u; ol[q][1] = 0u; }

        #pragma unroll
        for (int kk = 0; kk < 4; kk++) {
            uint32_t ahh[4] = {ph[2*kk][0], ph[2*kk][1], ph[2*kk+1][0], ph[2*kk+1][1]};
            uint32_t ahl[4] = {pl[2*kk][0], pl[2*kk][1], pl[2*kk+1][0], pl[2*kk+1][1]};
            #pragma unroll
            for (int qg = 0; qg < 2; qg++) {
                uint32_t vh[4][4];
                #pragma unroll
                for (int q = 0; q < 4; q++)
                    LDSM4T(vh[q], vb + v_off + kk * (16 * 272) + (qg * 4 + q) * 32);
                #pragma unroll
                for (int q = 0; q < 4; q++) {
                    mma_f16(o[2*(qg*4+q)],   ahh, vh[q][0], vh[q][1]);
                    mma_f16(o[2*(qg*4+q)+1], ahh, vh[q][2], vh[q][3]);
                }
                #pragma unroll
                for (int q = 0; q < 4; q++) {
                    mma_f16h(ol[2*(qg*4+q)],   ahl, vh[q][0], vh[q][1]);
                    mma_f16h(ol[2*(qg*4+q)+1], ahl, vh[q][2], vh[q][3]);
                }
            }
        }
        #pragma unroll
        for (int q = 0; q < 16; q++)
            fold2(o[q], ol[q][0], ol[q][1], SCINV);

        CP_WAIT0(); __syncthreads();
    }

    // epilogue: O /= l, split to fp16 hi + UNSCALED lo for the f32-acc WO GEMM
    float i0 = 1.f / lr0, i1 = 1.f / lr1;
    int r0 = t0 + w * 16 + (lane >> 2);
    size_t base0 = ((size_t)(b * TSEQ + r0)) * CDIM + h * HDIM + (lane & 3) * 2;
    size_t base1 = base0 + (size_t)8 * CDIM;
    #pragma unroll
    for (int q = 0; q < 16; q++) {
        float a0 = o[q][0] * i0, a1 = o[q][1] * i0;
        __half h0 = __float2half_rn(a0), h1 = __float2half_rn(a1);
        *(uint32_t*)(g_yhi + base0 + q * 8) =
            (uint32_t)__half_as_ushort(h0) | ((uint32_t)__half_as_ushort(h1) << 16);
        *(uint32_t*)(g_ylo + base0 + q * 8) =
            packh(a0 - __half2float(h0), a1 - __half2float(h1));
        float a2 = o[q][2] * i1, a3 = o[q][3] * i1;
        __half h2 = __float2half_rn(a2), h3 = __float2half_rn(a3);
        *(uint32_t*)(g_yhi + base1 + q * 8) =
            (uint32_t)__half_as_ushort(h2) | ((uint32_t)__half_as_ushort(h3) << 16);
        *(uint32_t*)(g_ylo + base1 + q * 8) =
            packh(a2 - __half2float(h2), a3 - __half2float(h3));
    }
}

// ---------------------------------------------------------------------------
extern "C" void kernel_launch(void* const* d_in, const int* in_sizes, int n_in,
                              void* d_out, int out_size)
{
    (void)in_sizes; (void)n_in; (void)out_size;
    const float* x    = (const float*)d_in[0];
    const float* cosp = (const float*)d_in[1];
    const float* sinp = (const float*)d_in[2];
    const float* wq   = (const float*)d_in[3];
    const float* wk   = (const float*)d_in[4];
    const float* wv   = (const float*)d_in[5];
    const float* wo   = (const float*)d_in[6];
    float* out = (float*)d_out;

    __half *xhi, *xlo, *wh;
    cudaGetSymbolAddress((void**)&xhi, g_xhi);
    cudaGetSymbolAddress((void**)&xlo, g_xlo);
    cudaGetSymbolAddress((void**)&wh,  g_wh);

    const size_t W = (size_t)CDIM * CDIM;
    const int n4x = MROWS * CDIM / 4;
    const int n4w = CDIM * CDIM / 4;

    // x lo stream UNSCALED (f32-acc gemm consumes it directly)
    split_kernel_noscale<<<n4x / 256, 256>>>(x, xhi, xlo, n4x);
    round_kernel<<<n4w / 256, 256>>>(wq, wh + 0 * W, n4w);
    round_kernel<<<n4w / 256, 256>>>(wk, wh + 1 * W, n4w);
    round_kernel<<<n4w / 256, 256>>>(wv, wh + 2 * W, n4w);
    round_kernel<<<n4w / 256, 256>>>(wo, wh + 3 * W, n4w);

    cudaFuncSetAttribute(gemm_fused,
                         cudaFuncAttributeMaxDynamicSharedMemorySize, G2_SMEM);
    cudaFuncSetAttribute(flash_mma,
                         cudaFuncAttributeMaxDynamicSharedMemorySize, FSMEM);

    // fused QKV: z = 0(Q,rope,2-term out) 1(K,rope,single) 2(V,single)
    // Q lo stream written SCALED (split2h) for flash's f16-acc residual path.
    gemm_fused<<<dim3(CDIM / 128, MROWS / 128, 3), 512, G2_SMEM>>>(0, cosp, sinp, out);

    flash_mma<<<dim3(TSEQ / 128, NHEAD, BATCH), 256, FSMEM>>>();

    // output projection (y lo stream is unscaled; f32-acc)
    gemm_fused<<<dim3(CDIM / 128, MROWS / 128, 1), 512, G2_SMEM>>>(1, cosp, sinp, out);
}